// round 2
// baseline (speedup 1.0000x reference)
#include <cuda_runtime.h>
#include <cstdint>

// ---------------- problem constants ----------------
#define B_    32
#define T_    300
#define FIN   3072
#define FH    410
#define FOUT  10
#define NTOT  (B_*T_*FIN)          // 29,491,200 spikes
#define THETA 10.0f
// exp(float32(-0.1)) correctly rounded to f32
#define DECAY 0.9048374166859746f

// PRNG mode: 1 = jax_threefry_partitionable (modern JAX default)
//            0 = legacy paired-counter mode (fallback if rel_err blows up)
#define PRNG_PARTITIONABLE 1

// ---------------- scratch (no allocations allowed) ----------------
__device__ uint8_t g_spikes[NTOT];            // [B,T,FIN] binary
__device__ float   g_a1[B_*T_*FH];            // layer-1 pre-activations
__device__ uint8_t g_s1[B_*T_*FH];            // layer-1 spikes

// ---------------- threefry-2x32 (20 rounds), matches JAX ----------------
__device__ __forceinline__ uint2 threefry2x32(uint32_t k0, uint32_t k1,
                                              uint32_t x0, uint32_t x1) {
    uint32_t ks2 = k0 ^ k1 ^ 0x1BD11BDAu;
    x0 += k0; x1 += k1;
#define TF_R(r) { x0 += x1; x1 = __funnelshift_l(x1, x1, (r)); x1 ^= x0; }
    TF_R(13) TF_R(15) TF_R(26) TF_R(6)   x0 += k1;  x1 += ks2 + 1u;
    TF_R(17) TF_R(29) TF_R(16) TF_R(24)  x0 += ks2; x1 += k0  + 2u;
    TF_R(13) TF_R(15) TF_R(26) TF_R(6)   x0 += k0;  x1 += k1  + 3u;
    TF_R(17) TF_R(29) TF_R(16) TF_R(24)  x0 += k1;  x1 += ks2 + 4u;
    TF_R(13) TF_R(15) TF_R(26) TF_R(6)   x0 += ks2; x1 += k0  + 5u;
#undef TF_R
    return make_uint2(x0, x1);
}

__device__ __forceinline__ float bits_to_uniform(uint32_t bits) {
    // jax.random.uniform float32 path: (bits>>9)|0x3f800000, bitcast, -1
    return __uint_as_float((bits >> 9) | 0x3F800000u) - 1.0f;
}

// ---------------- kernel 1: rate encoding ----------------
__global__ void k_gen_spikes(const float* __restrict__ inp) {
    uint32_t idx = blockIdx.x * blockDim.x + threadIdx.x;
    if (idx >= NTOT) return;
#if PRNG_PARTITIONABLE
    // counter = flat index (64-bit, hi word = 0); bits = low word of output
    uint2 r = threefry2x32(0u, 42u, 0u, idx);
    uint32_t bits = r.y;
#else
    // legacy: iota split in halves; pair (i, half+i) -> (out[i], out[half+i])
    const uint32_t half = NTOT / 2;
    uint32_t i = (idx < half) ? idx : (idx - half);
    uint2 r = threefry2x32(0u, 42u, i, half + i);
    uint32_t bits = (idx < half) ? r.x : r.y;
#endif
    float u = bits_to_uniform(bits);
    uint32_t b = idx / (T_ * FIN);
    uint32_t f = idx % FIN;
    float p = inp[b * FIN + f];
    g_spikes[idx] = (u < p) ? (uint8_t)1 : (uint8_t)0;
}

// ---------------- kernel 2: GEMM1  C[9600,410] = spikes[9600,3072] * W1^T ----
#define BM 128
#define BN 64
#define BK 32
__global__ __launch_bounds__(256, 2)
void k_gemm1(const float* __restrict__ W1) {
    __shared__ float As[BK][BM];   // k-major
    __shared__ float Bs[BK][BN];

    const int K = FIN;
    int tid   = threadIdx.x;
    int m_blk = blockIdx.y * BM;
    int n_blk = blockIdx.x * BN;

    // A load map: 128 rows x 32 bytes; 2 threads/row, 16B each
    int a_row = tid >> 1;
    int a_k   = (tid & 1) * 16;
    // B load map: 64 rows x 32 floats; 4 threads/row, 8 floats each
    int b_row = tid >> 2;
    int b_k   = (tid & 3) * 8;

    int ty = tid >> 4;     // 0..15, 8 rows each
    int tx = tid & 15;     // 0..15, 4 cols each

    float acc[8][4];
#pragma unroll
    for (int i = 0; i < 8; i++)
#pragma unroll
        for (int j = 0; j < 4; j++) acc[i][j] = 0.f;

    for (int k0 = 0; k0 < K; k0 += BK) {
        // --- load A tile (uint8 spikes -> float) ---
        uint4 av = *reinterpret_cast<const uint4*>(
            g_spikes + (size_t)(m_blk + a_row) * K + k0 + a_k);
        uint32_t w[4] = {av.x, av.y, av.z, av.w};
#pragma unroll
        for (int q = 0; q < 4; q++)
#pragma unroll
            for (int j = 0; j < 4; j++)
                As[a_k + q * 4 + j][a_row] = (float)((w[q] >> (8 * j)) & 0xFFu);

        // --- load B tile (W1, guard n<410) ---
        int n = n_blk + b_row;
        float4 v0 = make_float4(0.f, 0.f, 0.f, 0.f), v1 = v0;
        if (n < FH) {
            const float4* src = reinterpret_cast<const float4*>(
                W1 + (size_t)n * K + k0 + b_k);
            v0 = src[0]; v1 = src[1];
        }
        Bs[b_k + 0][b_row] = v0.x; Bs[b_k + 1][b_row] = v0.y;
        Bs[b_k + 2][b_row] = v0.z; Bs[b_k + 3][b_row] = v0.w;
        Bs[b_k + 4][b_row] = v1.x; Bs[b_k + 5][b_row] = v1.y;
        Bs[b_k + 6][b_row] = v1.z; Bs[b_k + 7][b_row] = v1.w;

        __syncthreads();

#pragma unroll
        for (int k = 0; k < BK; k++) {
            float4 a0 = *reinterpret_cast<const float4*>(&As[k][ty * 8]);
            float4 a1 = *reinterpret_cast<const float4*>(&As[k][ty * 8 + 4]);
            float4 bv = *reinterpret_cast<const float4*>(&Bs[k][tx * 4]);
            float a[8] = {a0.x, a0.y, a0.z, a0.w, a1.x, a1.y, a1.z, a1.w};
            float b[4] = {bv.x, bv.y, bv.z, bv.w};
#pragma unroll
            for (int i = 0; i < 8; i++)
#pragma unroll
                for (int j = 0; j < 4; j++)
                    acc[i][j] = fmaf(a[i], b[j], acc[i][j]);
        }
        __syncthreads();
    }

#pragma unroll
    for (int i = 0; i < 8; i++) {
        int m = m_blk + ty * 8 + i;
#pragma unroll
        for (int j = 0; j < 4; j++) {
            int n = n_blk + tx * 4 + j;
            if (n < FH) g_a1[(size_t)m * FH + n] = acc[i][j];
        }
    }
}

// ---------------- kernel 3: PSP scan + threshold (layer 1) ----------------
__global__ void k_scan1() {
    int gid = blockIdx.x * blockDim.x + threadIdx.x;
    if (gid >= B_ * FH) return;
    int b = gid / FH, o = gid % FH;
    const float* p = g_a1 + (size_t)b * T_ * FH + o;
    uint8_t*     q = g_s1 + (size_t)b * T_ * FH + o;
    float u = 0.f;
    float x = p[0];
    for (int t = 0; t < T_; t++) {
        float xn = (t + 1 < T_) ? p[(t + 1) * FH] : 0.f;   // prefetch
        u = __fadd_rn(__fmul_rn(DECAY, u), x);
        q[t * FH] = (u >= THETA) ? (uint8_t)1 : (uint8_t)0;
        x = xn;
    }
}

// ---------------- kernel 4: layer 2 + PSP scan + threshold + transpose -----
// grid = 32 (one block per batch), 320 threads (warp w -> output neuron w)
__global__ void k_layer2(const float* __restrict__ W2, float* __restrict__ out) {
    int b    = blockIdx.x;
    int w    = threadIdx.x >> 5;     // 0..9
    int lane = threadIdx.x & 31;

    float w2r[13];
#pragma unroll
    for (int j = 0; j < 13; j++) {
        int o = lane + 32 * j;
        w2r[j] = (o < FH) ? W2[w * FH + o] : 0.f;
    }

    const uint8_t* sp = g_s1 + (size_t)b * T_ * FH;
    float u = 0.f;
    for (int t = 0; t < T_; t++) {
        float acc = 0.f;
        const uint8_t* row = sp + (size_t)t * FH;
#pragma unroll
        for (int j = 0; j < 13; j++) {
            int o = lane + 32 * j;
            if (o < FH && row[o]) acc += w2r[j];
        }
#pragma unroll
        for (int off = 16; off; off >>= 1)
            acc += __shfl_down_sync(0xFFFFFFFFu, acc, off);
        if (lane == 0) {
            u = __fadd_rn(__fmul_rn(DECAY, u), acc);
            out[((size_t)b * FOUT + w) * T_ + t] = (u >= THETA) ? 1.f : 0.f;
        }
    }
}

// ---------------- launch ----------------
extern "C" void kernel_launch(void* const* d_in, const int* in_sizes, int n_in,
                              void* d_out, int out_size) {
    const float* inp = (const float*)d_in[0];   // [32,3,32,32] = 98304
    const float* W1  = (const float*)d_in[1];   // [410,3072]
    const float* W2  = (const float*)d_in[2];   // [10,410]
    float* out = (float*)d_out;                 // [32,10,300]

    k_gen_spikes<<<(NTOT + 255) / 256, 256>>>(inp);

    dim3 g1((FH + BN - 1) / BN, (B_ * T_) / BM);   // (7, 75)
    k_gemm1<<<g1, 256>>>(W1);

    k_scan1<<<(B_ * FH + 255) / 256, 256>>>();

    k_layer2<<<B_, 320>>>(W2, out);
}

// round 8
// speedup vs baseline: 2.0718x; 2.0718x over previous
#include <cuda_runtime.h>
#include <cuda_bf16.h>
#include <cstdint>

// ---------------- problem constants ----------------
#define B_    32
#define T_    300
#define FIN   3072
#define FH    410
#define FHP   448                  // FH padded to BN multiple
#define FOUT  10
#define NTOT  (B_*T_*FIN)          // 29,491,200
#define MTOT  (B_*T_)              // 9600
#define THETA 10.0f
#define DECAY 0.9048374166859746f  // exp(f32(-0.1))

// ---------------- GEMM1 tiling (mma.sync path, compute_103-safe) ----------
#define BM 128
#define BN 64
#define BK 64                      // bf16 per k-stage -> 128B rows
#define KBLKS (FIN/BK)             // 48
#define NSTAGE 3
#define STAGE_A (BM*128)           // 16384
#define STAGE_B (2*BN*128)         // 16384 (hi+mid splits)
#define STAGE_BYTES (STAGE_A + STAGE_B)        // 32768
#define GEMM1_SMEM  (NSTAGE*STAGE_BYTES)       // 98304

// ---------------- scratch ----------------
__device__ __align__(16) __nv_bfloat16 g_spkb[(size_t)MTOT*FIN];   // spikes bf16
__device__ __align__(16) __nv_bfloat16 g_w1b[2u*FHP*FIN];          // hi/mid splits
__device__ float   g_a1T[(size_t)FH*MTOT];    // a1 transposed [n][m]
__device__ uint8_t g_s1[(size_t)MTOT*FH];     // layer-1 spikes [m][o]
__device__ float   g_a2[(size_t)MTOT*FOUT];

// ---------------- PTX helpers (all >= compute_80) ----------------
__device__ __forceinline__ uint32_t s2u(const void* p) {
    uint32_t a;
    asm("{ .reg .u64 t; cvta.to.shared.u64 t, %1; cvt.u32.u64 %0, t; }"
        : "=r"(a) : "l"(p));
    return a;
}
__device__ __forceinline__ void cp16(uint32_t dst, const void* src) {
    asm volatile("cp.async.cg.shared.global [%0], [%1], 16;"
                 :: "r"(dst), "l"(src));
}
#define CP_COMMIT() asm volatile("cp.async.commit_group;" ::: "memory")
#define CP_WAIT(n)  asm volatile("cp.async.wait_group %0;" :: "n"(n) : "memory")

#define LDSM4(r, addr) \
    asm volatile("ldmatrix.sync.aligned.m8n8.x4.shared.b16 {%0,%1,%2,%3}, [%4];" \
        : "=r"((r)[0]), "=r"((r)[1]), "=r"((r)[2]), "=r"((r)[3]) : "r"(addr))

#define MMA16816(d, a, b0, b1) \
    asm volatile("mma.sync.aligned.m16n8k16.row.col.f32.bf16.bf16.f32 " \
        "{%0,%1,%2,%3}, {%4,%5,%6,%7}, {%8,%9}, {%0,%1,%2,%3};" \
        : "+f"((d)[0]), "+f"((d)[1]), "+f"((d)[2]), "+f"((d)[3]) \
        : "r"((a)[0]), "r"((a)[1]), "r"((a)[2]), "r"((a)[3]), "r"(b0), "r"(b1))

__device__ __forceinline__ uint32_t sw128(uint32_t off) {
    return off ^ ((off >> 3) & 0x70u);
}

// ---------------- threefry-2x32 (JAX partitionable mode, verified exact) ---
__device__ __forceinline__ uint2 threefry2x32(uint32_t k0, uint32_t k1,
                                              uint32_t x0, uint32_t x1) {
    uint32_t ks2 = k0 ^ k1 ^ 0x1BD11BDAu;
    x0 += k0; x1 += k1;
#define TF_R(r) { x0 += x1; x1 = __funnelshift_l(x1, x1, (r)); x1 ^= x0; }
    TF_R(13) TF_R(15) TF_R(26) TF_R(6)   x0 += k1;  x1 += ks2 + 1u;
    TF_R(17) TF_R(29) TF_R(16) TF_R(24)  x0 += ks2; x1 += k0  + 2u;
    TF_R(13) TF_R(15) TF_R(26) TF_R(6)   x0 += k0;  x1 += k1  + 3u;
    TF_R(17) TF_R(29) TF_R(16) TF_R(24)  x0 += k1;  x1 += ks2 + 4u;
    TF_R(13) TF_R(15) TF_R(26) TF_R(6)   x0 += ks2; x1 += k0  + 5u;
#undef TF_R
    return make_uint2(x0, x1);
}
__device__ __forceinline__ float bits_to_uniform(uint32_t bits) {
    return __uint_as_float((bits >> 9) | 0x3F800000u) - 1.0f;
}

// ---------------- kernel: W1 -> 2-way bf16 split (padded to 448 rows) -----
__global__ void k_split_w1(const float* __restrict__ W1) {
    int gid = blockIdx.x * blockDim.x + threadIdx.x;
    if (gid >= FHP * FIN) return;
    int n = gid / FIN, f = gid - n * FIN;
    float w = (n < FH) ? W1[n * FIN + f] : 0.f;
    __nv_bfloat16 h = __float2bfloat16(w);
    __nv_bfloat16 m = __float2bfloat16(w - __bfloat162float(h));
    g_w1b[gid] = h;
    g_w1b[(size_t)FHP * FIN + gid] = m;
}

// ---------------- kernel: rate encoding -> bf16 spikes ----------------
__global__ void k_gen_spikes(const float* __restrict__ inp) {
    uint32_t q = blockIdx.x * blockDim.x + threadIdx.x;
    if (q >= NTOT / 4) return;
    uint32_t idx0 = q * 4;
    uint32_t b = idx0 / (T_ * FIN);
    uint32_t f = idx0 % FIN;
    float4 p4 = *reinterpret_cast<const float4*>(inp + (size_t)b * FIN + f);
    float pv[4] = {p4.x, p4.y, p4.z, p4.w};
    uint32_t r[4];
#pragma unroll
    for (int j = 0; j < 4; j++) {
        uint2 h = threefry2x32(0u, 42u, 0u, idx0 + j);
        r[j] = (bits_to_uniform(h.y) < pv[j]) ? 0x3F80u : 0u;
    }
    uint2 o;
    o.x = r[0] | (r[1] << 16);
    o.y = r[2] | (r[3] << 16);
    *reinterpret_cast<uint2*>(g_spkb + idx0) = o;
}

// ---------------- GEMM1: a1T[n][m] = spikes[m][k] * (W1hi+W1mid)[n][k] ----
__device__ __forceinline__ void load_stage(uint32_t smb, int s, int kb,
                                           int m_blk, int n_blk, int tid) {
    uint32_t base = smb + s * STAGE_BYTES;
    int k0 = kb * BK;
    // A: 128 rows x 8 x 16B
#pragma unroll
    for (int it = 0; it < 4; it++) {
        int c = tid + it * 256;
        int row = c >> 3, cc = c & 7;
        uint32_t off = sw128(row * 128 + cc * 16);
        cp16(base + off,
             g_spkb + (size_t)(m_blk + row) * FIN + k0 + cc * 8);
    }
    // B: 2 splits x 64 rows x 8 x 16B
#pragma unroll
    for (int it = 0; it < 4; it++) {
        int c = tid + it * 256;
        int sp = c >> 9, row = (c >> 3) & 63, cc = c & 7;
        uint32_t off = sw128(row * 128 + cc * 16);
        cp16(base + STAGE_A + sp * (BN * 128) + off,
             g_w1b + (size_t)sp * FHP * FIN + (size_t)(n_blk + row) * FIN
                   + k0 + cc * 8);
    }
    CP_COMMIT();
}

__global__ __launch_bounds__(256, 2) void k_gemm1() {
    extern __shared__ char sm[];
    uint32_t smb = s2u(sm);
    int tid = threadIdx.x, wid = tid >> 5, lane = tid & 31;
    int m_blk = blockIdx.y * BM;
    int n_blk = blockIdx.x * BN;
    int mw = (wid & 3) * 32;       // warp m offset
    int nw = (wid >> 2) * 32;      // warp n offset

    float acc[2][4][4];
#pragma unroll
    for (int i = 0; i < 2; i++)
#pragma unroll
        for (int j = 0; j < 4; j++)
#pragma unroll
            for (int r = 0; r < 4; r++) acc[i][j][r] = 0.f;

    load_stage(smb, 0, 0, m_blk, n_blk, tid);
    load_stage(smb, 1, 1, m_blk, n_blk, tid);

    for (int kb = 0; kb < KBLKS; kb++) {
        if (kb + NSTAGE - 1 < KBLKS) { CP_WAIT(NSTAGE - 2); }
        else                         { CP_WAIT(0); }
        __syncthreads();
        if (kb + NSTAGE - 1 < KBLKS)
            load_stage(smb, (kb + NSTAGE - 1) % NSTAGE, kb + NSTAGE - 1,
                       m_blk, n_blk, tid);

        uint32_t Ab = smb + (kb % NSTAGE) * STAGE_BYTES;
        uint32_t Bb = Ab + STAGE_A;

#pragma unroll
        for (int kk = 0; kk < 4; kk++) {
            uint32_t af[2][4];
#pragma unroll
            for (int i = 0; i < 2; i++) {
                int row = mw + i * 16 + (lane & 15);
                int coff = (kk * 2 + (lane >> 4)) * 16;
                LDSM4(af[i], Ab + sw128(row * 128 + coff));
            }
#pragma unroll
            for (int sp = 0; sp < 2; sp++) {
                uint32_t bf[2][4];
#pragma unroll
                for (int jj = 0; jj < 2; jj++) {
                    int nrow = nw + jj * 16 + ((lane & 16) >> 1) + (lane & 7);
                    int coff = (kk * 2 + ((lane >> 3) & 1)) * 16;
                    LDSM4(bf[jj], Bb + sp * (BN * 128)
                                     + sw128(nrow * 128 + coff));
                }
#pragma unroll
                for (int i = 0; i < 2; i++) {
#pragma unroll
                    for (int j = 0; j < 4; j++) {
                        uint32_t b0 = (j & 1) ? bf[j >> 1][2] : bf[j >> 1][0];
                        uint32_t b1 = (j & 1) ? bf[j >> 1][3] : bf[j >> 1][1];
                        MMA16816(acc[i][j], af[i], b0, b1);
                    }
                }
            }
        }
        __syncthreads();
    }

    // epilogue: write transposed a1T[n][m]
    int g = lane >> 2, t4 = lane & 3;
#pragma unroll
    for (int i = 0; i < 2; i++) {
#pragma unroll
        for (int j = 0; j < 4; j++) {
            int m0 = m_blk + mw + i * 16 + g;
            int n0 = n_blk + nw + j * 8 + t4 * 2;
            if (n0 < FH)     g_a1T[(size_t)n0 * MTOT + m0]       = acc[i][j][0];
            if (n0 + 1 < FH) g_a1T[(size_t)(n0+1) * MTOT + m0]   = acc[i][j][1];
            if (n0 < FH)     g_a1T[(size_t)n0 * MTOT + m0 + 8]   = acc[i][j][2];
            if (n0 + 1 < FH) g_a1T[(size_t)(n0+1) * MTOT + m0+8] = acc[i][j][3];
        }
    }
}

// ---------------- PSP scan + threshold (layer 1) ----------------
__global__ void k_scan1() {
    int gid = blockIdx.x * blockDim.x + threadIdx.x;
    if (gid >= B_ * FH) return;
    int o = gid % FH, b = gid / FH;
    const float4* p = reinterpret_cast<const float4*>(
        g_a1T + (size_t)o * MTOT + b * T_);
    uint8_t* q = g_s1 + (size_t)b * T_ * FH + o;
    float u = 0.f;
    for (int i = 0; i < T_ / 4; i++) {
        float4 v = p[i];
        u = __fadd_rn(__fmul_rn(DECAY, u), v.x); q[(4*i+0)*FH] = (u >= THETA);
        u = __fadd_rn(__fmul_rn(DECAY, u), v.y); q[(4*i+1)*FH] = (u >= THETA);
        u = __fadd_rn(__fmul_rn(DECAY, u), v.z); q[(4*i+2)*FH] = (u >= THETA);
        u = __fadd_rn(__fmul_rn(DECAY, u), v.w); q[(4*i+3)*FH] = (u >= THETA);
    }
}

// ---------------- layer 2 GEMM (warp per (b,t) row) ----------------
__global__ __launch_bounds__(256) void k_gemm2(const float* __restrict__ W2) {
    __shared__ float w2s[FOUT * FH];
    for (int i = threadIdx.x; i < FOUT * FH; i += 256) w2s[i] = W2[i];
    __syncthreads();
    int w = threadIdx.x >> 5, lane = threadIdx.x & 31;
    int m = blockIdx.x * 8 + w;
    const uint8_t* row = g_s1 + (size_t)m * FH;
    float acc[FOUT];
#pragma unroll
    for (int i = 0; i < FOUT; i++) acc[i] = 0.f;
#pragma unroll
    for (int j = 0; j < 13; j++) {
        int o = j * 32 + lane;
        if (o < FH && row[o]) {
#pragma unroll
            for (int i = 0; i < FOUT; i++) acc[i] += w2s[i * FH + o];
        }
    }
#pragma unroll
    for (int i = 0; i < FOUT; i++) {
        float v = acc[i];
#pragma unroll
        for (int off = 16; off; off >>= 1)
            v += __shfl_down_sync(0xFFFFFFFFu, v, off);
        if (lane == 0) g_a2[(size_t)m * FOUT + i] = v;
    }
}

// ---------------- layer 2 scan + transpose ----------------
__global__ void k_scan2(float* __restrict__ out) {
    int gid = blockIdx.x * blockDim.x + threadIdx.x;
    if (gid >= B_ * FOUT) return;
    int b = gid / FOUT, o = gid % FOUT;
    const float* p = g_a2 + (size_t)b * T_ * FOUT + o;
    float* q = out + (size_t)b * FOUT * T_ + (size_t)o * T_;
    float u = 0.f, x = p[0];
    for (int t = 0; t < T_; t++) {
        float xn = (t + 1 < T_) ? p[(t + 1) * FOUT] : 0.f;
        u = __fadd_rn(__fmul_rn(DECAY, u), x);
        q[t] = (u >= THETA) ? 1.f : 0.f;
        x = xn;
    }
}

// ---------------- launch ----------------
extern "C" void kernel_launch(void* const* d_in, const int* in_sizes, int n_in,
                              void* d_out, int out_size) {
    const float* inp = (const float*)d_in[0];   // [32,3,32,32]
    const float* W1  = (const float*)d_in[1];   // [410,3072]
    const float* W2  = (const float*)d_in[2];   // [10,410]
    float* out = (float*)d_out;                 // [32,10,300]

    static int smem_set = 0;
    if (!smem_set) {
        cudaFuncSetAttribute(k_gemm1,
            cudaFuncAttributeMaxDynamicSharedMemorySize, GEMM1_SMEM);
        smem_set = 1;
    }

    k_split_w1<<<(FHP * FIN + 255) / 256, 256>>>(W1);
    k_gen_spikes<<<(NTOT / 4 + 255) / 256, 256>>>(inp);

    dim3 g1(FHP / BN, MTOT / BM);               // (7, 75)
    k_gemm1<<<g1, 256, GEMM1_SMEM>>>();

    k_scan1<<<(B_ * FH + 255) / 256, 256>>>();
    k_gemm2<<<MTOT / 8, 256>>>(W2);
    k_scan2<<<(B_ * FOUT + 31) / 32, 32>>>(out);
}

// round 9
// speedup vs baseline: 2.9221x; 1.4104x over previous
#include <cuda_runtime.h>
#include <cuda_bf16.h>
#include <cstdint>

// ---------------- problem constants ----------------
#define B_    32
#define T_    300
#define FIN   3072
#define FH    410
#define FHP   448                  // FH padded to BN multiple
#define FOUT  10
#define NTOT  (B_*T_*FIN)          // 29,491,200
#define MTOT  (B_*T_)              // 9600
#define MTOTP 9728                 // padded to BM multiple (38*256)
#define THETA 10.0f
#define DECAY 0.9048374166859746f  // exp(f32(-0.1))

// ---------------- GEMM1 tiling ----------------
#define BM 256
#define BN 64
#define BK 64                      // bf16 per k-stage -> 128B rows
#define KBLKS (FIN/BK)             // 48
#define NSTAGE 3
#define STAGE_A (BM*128)           // 32768
#define STAGE_B (2*BN*128)         // 16384 (hi+mid splits)
#define STAGE_BYTES (STAGE_A + STAGE_B)        // 49152
#define GEMM1_SMEM  (NSTAGE*STAGE_BYTES)       // 147456

// ---------------- scratch ----------------
__device__ __align__(16) __nv_bfloat16 g_spkb[(size_t)MTOTP*FIN]; // spikes bf16 (pad rows stay 0)
__device__ __align__(16) __nv_bfloat16 g_w1b[2u*FHP*FIN];         // hi/mid splits
__device__ float   g_a1T[(size_t)FH*MTOT];     // a1 transposed [n][m]
__device__ __align__(4) uint8_t g_s1T[(size_t)B_*FH*T_];  // layer-1 spikes [b][o][t]
__device__ float   g_a2[(size_t)MTOT*FOUT];    // [b*t][i]

// ---------------- PTX helpers (all >= compute_80) ----------------
__device__ __forceinline__ uint32_t s2u(const void* p) {
    uint32_t a;
    asm("{ .reg .u64 t; cvta.to.shared.u64 t, %1; cvt.u32.u64 %0, t; }"
        : "=r"(a) : "l"(p));
    return a;
}
__device__ __forceinline__ void cp16(uint32_t dst, const void* src) {
    asm volatile("cp.async.cg.shared.global [%0], [%1], 16;"
                 :: "r"(dst), "l"(src));
}
#define CP_COMMIT() asm volatile("cp.async.commit_group;" ::: "memory")
#define CP_WAIT(n)  asm volatile("cp.async.wait_group %0;" :: "n"(n) : "memory")

#define LDSM4(r, addr) \
    asm volatile("ldmatrix.sync.aligned.m8n8.x4.shared.b16 {%0,%1,%2,%3}, [%4];" \
        : "=r"((r)[0]), "=r"((r)[1]), "=r"((r)[2]), "=r"((r)[3]) : "r"(addr))

#define MMA16816(d, a, b0, b1) \
    asm volatile("mma.sync.aligned.m16n8k16.row.col.f32.bf16.bf16.f32 " \
        "{%0,%1,%2,%3}, {%4,%5,%6,%7}, {%8,%9}, {%0,%1,%2,%3};" \
        : "+f"((d)[0]), "+f"((d)[1]), "+f"((d)[2]), "+f"((d)[3]) \
        : "r"((a)[0]), "r"((a)[1]), "r"((a)[2]), "r"((a)[3]), "r"(b0), "r"(b1))

__device__ __forceinline__ uint32_t sw128(uint32_t off) {
    return off ^ ((off >> 3) & 0x70u);
}

// ---------------- threefry-2x32 (JAX partitionable mode, verified exact) ---
__device__ __forceinline__ uint2 threefry2x32(uint32_t k0, uint32_t k1,
                                              uint32_t x0, uint32_t x1) {
    uint32_t ks2 = k0 ^ k1 ^ 0x1BD11BDAu;
    x0 += k0; x1 += k1;
#define TF_R(r) { x0 += x1; x1 = __funnelshift_l(x1, x1, (r)); x1 ^= x0; }
    TF_R(13) TF_R(15) TF_R(26) TF_R(6)   x0 += k1;  x1 += ks2 + 1u;
    TF_R(17) TF_R(29) TF_R(16) TF_R(24)  x0 += ks2; x1 += k0  + 2u;
    TF_R(13) TF_R(15) TF_R(26) TF_R(6)   x0 += k0;  x1 += k1  + 3u;
    TF_R(17) TF_R(29) TF_R(16) TF_R(24)  x0 += k1;  x1 += ks2 + 4u;
    TF_R(13) TF_R(15) TF_R(26) TF_R(6)   x0 += ks2; x1 += k0  + 5u;
#undef TF_R
    return make_uint2(x0, x1);
}
__device__ __forceinline__ float bits_to_uniform(uint32_t bits) {
    return __uint_as_float((bits >> 9) | 0x3F800000u) - 1.0f;
}

// ---------------- kernel: W1 -> 2-way bf16 split (padded to 448 rows) -----
__global__ void k_split_w1(const float* __restrict__ W1) {
    int gid = blockIdx.x * blockDim.x + threadIdx.x;
    if (gid >= FHP * FIN) return;
    int n = gid / FIN, f = gid - n * FIN;
    float w = (n < FH) ? W1[n * FIN + f] : 0.f;
    __nv_bfloat16 h = __float2bfloat16(w);
    __nv_bfloat16 m = __float2bfloat16(w - __bfloat162float(h));
    g_w1b[gid] = h;
    g_w1b[(size_t)FHP * FIN + gid] = m;
}

// ---------------- kernel: rate encoding -> bf16 spikes ----------------
__global__ void k_gen_spikes(const float* __restrict__ inp) {
    uint32_t q = blockIdx.x * blockDim.x + threadIdx.x;
    if (q >= NTOT / 4) return;
    uint32_t idx0 = q * 4;
    uint32_t b = idx0 / (T_ * FIN);
    uint32_t f = idx0 % FIN;
    float4 p4 = *reinterpret_cast<const float4*>(inp + (size_t)b * FIN + f);
    float pv[4] = {p4.x, p4.y, p4.z, p4.w};
    uint32_t r[4];
#pragma unroll
    for (int j = 0; j < 4; j++) {
        uint2 h = threefry2x32(0u, 42u, 0u, idx0 + j);
        r[j] = (bits_to_uniform(h.y) < pv[j]) ? 0x3F80u : 0u;
    }
    uint2 o;
    o.x = r[0] | (r[1] << 16);
    o.y = r[2] | (r[3] << 16);
    *reinterpret_cast<uint2*>(g_spkb + idx0) = o;
}

// ---------------- GEMM1: a1T[n][m] = spikes[m][k] * (W1hi+W1mid)[n][k] ----
__device__ __forceinline__ void load_stage(uint32_t smb, int s, int kb,
                                           int m_blk, int n_blk, int tid) {
    uint32_t base = smb + s * STAGE_BYTES;
    int k0 = kb * BK;
    // A: 256 rows x 8 x 16B
#pragma unroll
    for (int it = 0; it < 8; it++) {
        int c = tid + it * 256;
        int row = c >> 3, cc = c & 7;
        uint32_t off = sw128(row * 128 + cc * 16);
        cp16(base + off,
             g_spkb + (size_t)(m_blk + row) * FIN + k0 + cc * 8);
    }
    // B: 2 splits x 64 rows x 8 x 16B
#pragma unroll
    for (int it = 0; it < 4; it++) {
        int c = tid + it * 256;
        int sp = c >> 9, row = (c >> 3) & 63, cc = c & 7;
        uint32_t off = sw128(row * 128 + cc * 16);
        cp16(base + STAGE_A + sp * (BN * 128) + off,
             g_w1b + (size_t)sp * FHP * FIN + (size_t)(n_blk + row) * FIN
                   + k0 + cc * 8);
    }
    CP_COMMIT();
}

__global__ __launch_bounds__(256, 1) void k_gemm1() {
    extern __shared__ char sm[];
    uint32_t smb = s2u(sm);
    int tid = threadIdx.x, wid = tid >> 5, lane = tid & 31;
    int m_blk = blockIdx.y * BM;
    int n_blk = blockIdx.x * BN;
    int mw = (wid & 3) * 64;       // warp m offset (4 m-warps x 64)
    int nw = (wid >> 2) * 32;      // warp n offset (2 n-warps x 32)

    float acc[4][4][4];
#pragma unroll
    for (int i = 0; i < 4; i++)
#pragma unroll
        for (int j = 0; j < 4; j++)
#pragma unroll
            for (int r = 0; r < 4; r++) acc[i][j][r] = 0.f;

    load_stage(smb, 0, 0, m_blk, n_blk, tid);
    load_stage(smb, 1, 1, m_blk, n_blk, tid);

    for (int kb = 0; kb < KBLKS; kb++) {
        CP_WAIT(1);
        __syncthreads();
        // issue next stage's loads before compute (always commit a group)
        if (kb + 2 < KBLKS)
            load_stage(smb, (kb + 2) % NSTAGE, kb + 2, m_blk, n_blk, tid);
        else
            CP_COMMIT();

        uint32_t Ab = smb + (kb % NSTAGE) * STAGE_BYTES;
        uint32_t Bb = Ab + STAGE_A;

#pragma unroll
        for (int kk = 0; kk < 4; kk++) {
            uint32_t af[4][4];
#pragma unroll
            for (int i = 0; i < 4; i++) {
                int row = mw + i * 16 + (lane & 15);
                int coff = (kk * 2 + (lane >> 4)) * 16;
                LDSM4(af[i], Ab + sw128(row * 128 + coff));
            }
#pragma unroll
            for (int sp = 0; sp < 2; sp++) {
                uint32_t bf[2][4];
#pragma unroll
                for (int jj = 0; jj < 2; jj++) {
                    int nrow = nw + jj * 16 + ((lane & 16) >> 1) + (lane & 7);
                    int coff = (kk * 2 + ((lane >> 3) & 1)) * 16;
                    LDSM4(bf[jj], Bb + sp * (BN * 128)
                                     + sw128(nrow * 128 + coff));
                }
#pragma unroll
                for (int i = 0; i < 4; i++) {
#pragma unroll
                    for (int j = 0; j < 4; j++) {
                        uint32_t b0 = (j & 1) ? bf[j >> 1][2] : bf[j >> 1][0];
                        uint32_t b1 = (j & 1) ? bf[j >> 1][3] : bf[j >> 1][1];
                        MMA16816(acc[i][j], af[i], b0, b1);
                    }
                }
            }
        }
        // no trailing sync: next iteration's barrier protects stage reuse
    }

    // epilogue: write transposed a1T[n][m]
    int g = lane >> 2, t4 = lane & 3;
#pragma unroll
    for (int i = 0; i < 4; i++) {
#pragma unroll
        for (int j = 0; j < 4; j++) {
            int m0 = m_blk + mw + i * 16 + g;
            int n0 = n_blk + nw + j * 8 + t4 * 2;
            if (m0 < MTOT) {
                if (n0 < FH)     g_a1T[(size_t)n0 * MTOT + m0]     = acc[i][j][0];
                if (n0 + 1 < FH) g_a1T[(size_t)(n0+1) * MTOT + m0] = acc[i][j][1];
            }
            if (m0 + 8 < MTOT) {
                if (n0 < FH)     g_a1T[(size_t)n0 * MTOT + m0 + 8]     = acc[i][j][2];
                if (n0 + 1 < FH) g_a1T[(size_t)(n0+1) * MTOT + m0 + 8] = acc[i][j][3];
            }
        }
    }
}

// ---------------- PSP scan + threshold (layer 1), writes [b][o][t] --------
__global__ void k_scan1() {
    int gid = blockIdx.x * blockDim.x + threadIdx.x;
    if (gid >= B_ * FH) return;
    int o = gid % FH, b = gid / FH;
    const float4* p = reinterpret_cast<const float4*>(
        g_a1T + (size_t)o * MTOT + b * T_);
    uint32_t* q = reinterpret_cast<uint32_t*>(
        g_s1T + ((size_t)b * FH + o) * T_);
    float u = 0.f;
#pragma unroll 5
    for (int i = 0; i < T_ / 4; i++) {
        float4 v = p[i];
        uint32_t pk = 0;
        u = __fadd_rn(__fmul_rn(DECAY, u), v.x); pk  = (u >= THETA) ? 1u : 0u;
        u = __fadd_rn(__fmul_rn(DECAY, u), v.y); pk |= (u >= THETA) ? 0x100u : 0u;
        u = __fadd_rn(__fmul_rn(DECAY, u), v.z); pk |= (u >= THETA) ? 0x10000u : 0u;
        u = __fadd_rn(__fmul_rn(DECAY, u), v.w); pk |= (u >= THETA) ? 0x1000000u : 0u;
        q[i] = pk;
    }
}

// ---------------- layer 2 GEMM: thread per (b,t) ----------------
__global__ __launch_bounds__(320) void k_gemm2(const float* __restrict__ W2) {
    __shared__ float w2s[FOUT * FH];
    for (int i = threadIdx.x; i < FOUT * FH; i += 320) w2s[i] = W2[i];
    __syncthreads();
    int b = blockIdx.x;
    int t = threadIdx.x;
    if (t >= T_) return;
    const uint8_t* sp = g_s1T + (size_t)b * FH * T_;
    float acc[FOUT];
#pragma unroll
    for (int i = 0; i < FOUT; i++) acc[i] = 0.f;
#pragma unroll 4
    for (int o = 0; o < FH; o++) {
        float s = (float)sp[(size_t)o * T_ + t];
#pragma unroll
        for (int i = 0; i < FOUT; i++)
            acc[i] = fmaf(s, w2s[i * FH + o], acc[i]);
    }
    float* dst = g_a2 + ((size_t)b * T_ + t) * FOUT;
#pragma unroll
    for (int i = 0; i < FOUT; i++) dst[i] = acc[i];
}

// ---------------- layer 2 scan + transpose ----------------
__global__ void k_scan2(float* __restrict__ out) {
    int gid = blockIdx.x * blockDim.x + threadIdx.x;
    if (gid >= B_ * FOUT) return;
    int b = gid / FOUT, o = gid % FOUT;
    const float* p = g_a2 + (size_t)b * T_ * FOUT + o;
    float* q = out + (size_t)b * FOUT * T_ + (size_t)o * T_;
    float u = 0.f, x = p[0];
    for (int t = 0; t < T_; t++) {
        float xn = (t + 1 < T_) ? p[(t + 1) * FOUT] : 0.f;
        u = __fadd_rn(__fmul_rn(DECAY, u), x);
        q[t] = (u >= THETA) ? 1.f : 0.f;
        x = xn;
    }
}

// ---------------- launch ----------------
extern "C" void kernel_launch(void* const* d_in, const int* in_sizes, int n_in,
                              void* d_out, int out_size) {
    const float* inp = (const float*)d_in[0];   // [32,3,32,32]
    const float* W1  = (const float*)d_in[1];   // [410,3072]
    const float* W2  = (const float*)d_in[2];   // [10,410]
    float* out = (float*)d_out;                 // [32,10,300]

    static int smem_set = 0;
    if (!smem_set) {
        cudaFuncSetAttribute(k_gemm1,
            cudaFuncAttributeMaxDynamicSharedMemorySize, GEMM1_SMEM);
        smem_set = 1;
    }

    k_split_w1<<<(FHP * FIN + 255) / 256, 256>>>(W1);
    k_gen_spikes<<<(NTOT / 4 + 255) / 256, 256>>>(inp);

    dim3 g1(FHP / BN, MTOTP / BM);              // (7, 38)
    k_gemm1<<<g1, 256, GEMM1_SMEM>>>();

    k_scan1<<<(B_ * FH + 127) / 128, 128>>>();
    k_gemm2<<<B_, 320>>>(W2);
    k_scan2<<<(B_ * FOUT + 31) / 32, 32>>>(out);
}